// round 13
// baseline (speedup 1.0000x reference)
#include <cuda_runtime.h>
#include <cuda_fp16.h>
#include <cstdint>

#define NN 100000
#define EE 600000

// ---------------- scratch (static device globals; no runtime alloc) ----------
__device__ __half g_hbufA[NN * 128];  // fp16 GEMM inputs (agg outputs, H1)
__device__ __half g_hbuf[NN * 128];   // fp16 GEMM outputs (gather source)
__device__ float  g_score[NN];        // layer-5 per-node score
__device__ float  g_ax[NN * 3];
__device__ float4 g_x4[NN];           // padded copy of x for 16B gathers
__device__ int    g_cnt[NN];          // zero at load; re-zeroed by k_fill each run
__device__ int    g_rowptr[NN + 1];
__device__ float  g_dis[NN];
__device__ int2   g_edge[EE];         // CSR record: {src, __float_as_int(weight)}
__device__ int    g_rank[EE];
__device__ int    g_bsum[98];
__device__ unsigned g_barcnt = 0;
__device__ volatile unsigned g_barrel = 0;
// pre-transposed fp16 weight images: [n][k], row stride K+8 halves
__device__ __align__(16) __half g_hW2[128 * 136];
__device__ __align__(16) __half g_hW3[64 * 136];
__device__ __align__(16) __half g_hW4[64 * 72];

// ---------------- helpers ------------------------------------------------------
__device__ __forceinline__ void mma16816(float* c, const uint32_t* a, const uint32_t* b) {
    asm volatile(
        "mma.sync.aligned.m16n8k16.row.col.f32.f16.f16.f32 "
        "{%0,%1,%2,%3}, {%4,%5,%6,%7}, {%8,%9}, {%0,%1,%2,%3};"
        : "+f"(c[0]), "+f"(c[1]), "+f"(c[2]), "+f"(c[3])
        : "r"(a[0]), "r"(a[1]), "r"(a[2]), "r"(a[3]), "r"(b[0]), "r"(b[1]));
}
#define LDSM4(R0, R1, R2, R3, ADDR) \
    asm volatile("ldmatrix.sync.aligned.m8n8.x4.shared.b16 {%0,%1,%2,%3}, [%4];" \
                 : "=r"(R0), "=r"(R1), "=r"(R2), "=r"(R3) : "r"(ADDR))
// grid barrier; all blocks co-resident (<=148). Epoch-based, self-resetting,
// replay-safe (proven in k_scan since R6).
__device__ __forceinline__ void gbar(unsigned nb) {
    __threadfence();
    __syncthreads();
    if (threadIdx.x == 0) {
        unsigned epoch = g_barrel;
        if (atomicAdd(&g_barcnt, 1u) == nb - 1u) {
            g_barcnt = 0;
            __threadfence();
            g_barrel = epoch + 1;
        } else {
            while (g_barrel == epoch) {}
        }
    }
    __syncthreads();
}

// ---------------- hist (+ weight prep & x packing piggyback) ------------------
__global__ void k_hist(const int* __restrict__ ei, const float* __restrict__ x,
                       const float* __restrict__ W2, const float* __restrict__ W3,
                       const float* __restrict__ W4) {
    int e = blockIdx.x * blockDim.x + threadIdx.x;
    if (e < 128 * 128) {                   // W2: K=128, M=128
        int n = e >> 7, k = e & 127;
        g_hW2[n * 136 + k] = __float2half_rn(W2[k * 128 + n]);
    }
    if (e < 64 * 128) {                    // W3: K=128, M=64
        int n = e >> 7, k = e & 127;
        g_hW3[n * 136 + k] = __float2half_rn(W3[k * 64 + n]);
    }
    if (e < 64 * 64) {                     // W4: K=64, M=64
        int n = e >> 6, k = e & 63;
        g_hW4[n * 72 + k] = __float2half_rn(W4[k * 64 + n]);
    }
    if (e < NN)                            // pack x rows to 16B
        g_x4[e] = make_float4(x[e * 3 + 0], x[e * 3 + 1], x[e * 3 + 2], 0.f);
    if (e >= EE) return;
    int c = ei[EE + e];
    g_rank[e] = atomicAdd(&g_cnt[c], 1);
}
__global__ void __launch_bounds__(1024) k_scan() {
    const int t = threadIdx.x;
    const int lane = t & 31;
    const int w = t >> 5;
    const int i = blockIdx.x * 1024 + t;
    int v = (i < NN) ? g_cnt[i] : 0;

    int sc = v;
#pragma unroll
    for (int o = 1; o < 32; o <<= 1) {
        int u = __shfl_up_sync(0xFFFFFFFFu, sc, o);
        if (lane >= o) sc += u;
    }
    __shared__ int wsum[32];
    if (lane == 31) wsum[w] = sc;
    __syncthreads();
    if (w == 0) {
        int ws = wsum[lane];
#pragma unroll
        for (int o = 1; o < 32; o <<= 1) {
            int u = __shfl_up_sync(0xFFFFFFFFu, ws, o);
            if (lane >= o) ws += u;
        }
        wsum[lane] = ws;
    }
    __syncthreads();
    int incl = sc + ((w > 0) ? wsum[w - 1] : 0);
    if (t == 0) g_bsum[blockIdx.x] = wsum[31];

    gbar(98);

    __shared__ int red[128];
    if (t < 128) red[t] = (t < blockIdx.x) ? g_bsum[t] : 0;
    __syncthreads();
#pragma unroll
    for (int o = 64; o > 0; o >>= 1) {
        if (t < o) red[t] += red[t + o];
        __syncthreads();
    }
    int excl = incl - v + red[0];
    if (i < NN) {
        g_rowptr[i] = excl;
        g_dis[i] = rsqrtf((float)(v + 1));
    }
    if (i == NN - 1) g_rowptr[NN] = excl + v;
}
__global__ void k_fill(const int* __restrict__ ei) {
    int e = blockIdx.x * blockDim.x + threadIdx.x;
    if (e < NN) g_cnt[e] = 0;
    if (e >= EE) return;
    int r = ei[e];
    int c = ei[EE + e];
    int p = g_rowptr[c] + g_rank[e];
    g_edge[p] = make_int2(r, __float_as_int(g_dis[r] * g_dis[c]));
}

// ---------------- aggregation kernels (gather, atomic-free) ------------------
__global__ void k_agg0() {
    int i = blockIdx.x * blockDim.x + threadIdx.x;
    if (i >= NN) return;
    float d = g_dis[i];
    float inv = d * d;
    float4 sx = g_x4[i];
    float a0 = sx.x * inv;
    float a1 = sx.y * inv;
    float a2 = sx.z * inv;
    int p1 = g_rowptr[i + 1];
    for (int p = g_rowptr[i]; p < p1; p++) {
        int2 eg = g_edge[p];
        float w = __int_as_float(eg.y);
        float4 v = g_x4[eg.x];
        a0 += w * v.x;
        a1 += w * v.y;
        a2 += w * v.z;
    }
    g_ax[i * 3 + 0] = a0;
    g_ax[i * 3 + 1] = a1;
    g_ax[i * 3 + 2] = a2;
}
__global__ void k_agg128() {
    int node = blockIdx.x * 8 + (threadIdx.x >> 5);
    if (node >= NN) return;
    int lane = threadIdx.x & 31;
    int off = lane * 4;
    float d = g_dis[node];
    float inv = d * d;
    uint2 su = *(const uint2*)&g_hbuf[node * 128 + off];
    float2 s01 = __half22float2(*(__half2*)&su.x);
    float2 s23 = __half22float2(*(__half2*)&su.y);
    float ax = s01.x * inv, ay = s01.y * inv, az = s23.x * inv, aw = s23.y * inv;
    int p1 = g_rowptr[node + 1];
    for (int p = g_rowptr[node]; p < p1; p++) {
        int2 eg = g_edge[p];
        int s = eg.x;
        float w = __int_as_float(eg.y);
        uint2 u = *(const uint2*)&g_hbuf[s * 128 + off];
        float2 v01 = __half22float2(*(__half2*)&u.x);
        float2 v23 = __half22float2(*(__half2*)&u.y);
        ax += w * v01.x; ay += w * v01.y; az += w * v23.x; aw += w * v23.y;
    }
    uint2 o;
    *(__half2*)&o.x = __floats2half2_rn(ax, ay);
    *(__half2*)&o.y = __floats2half2_rn(az, aw);
    *(uint2*)&g_hbufA[node * 128 + off] = o;
}
__global__ void k_agg64() {
    int node = blockIdx.x * 8 + (threadIdx.x >> 5);
    if (node >= NN) return;
    int lane = threadIdx.x & 31;
    int off = lane * 2;
    float d = g_dis[node];
    float inv = d * d;
    float2 s01 = __half22float2(*(const __half2*)&g_hbuf[node * 64 + off]);
    float ax = s01.x * inv, ay = s01.y * inv;
    int p1 = g_rowptr[node + 1];
    for (int p = g_rowptr[node]; p < p1; p++) {
        int2 eg = g_edge[p];
        int s = eg.x;
        float w = __int_as_float(eg.y);
        float2 v = __half22float2(*(const __half2*)&g_hbuf[s * 64 + off]);
        ax += w * v.x; ay += w * v.y;
    }
    *(__half2*)&g_hbufA[node * 64 + off] = __floats2half2_rn(ax, ay);
}

// ---------------- small GEMM (layer 1, SIMT) ----------------------------------
__global__ void k_gemm1(const float* __restrict__ W1, const float* __restrict__ b1) {
    __shared__ float ws[3 * 128];
    __shared__ float bs[128];
    for (int i = threadIdx.x; i < 384; i += 256) ws[i] = W1[i];
    if (threadIdx.x < 128) bs[threadIdx.x] = b1[threadIdx.x];
    __syncthreads();
    int gid = blockIdx.x * 256 + threadIdx.x;
    int row = gid >> 5;
    int c = (gid & 31) * 4;
    if (row >= NN) return;
    float a0 = g_ax[row * 3 + 0];
    float a1 = g_ax[row * 3 + 1];
    float a2 = g_ax[row * 3 + 2];
    float ox = fmaxf(bs[c + 0] + a0 * ws[c + 0] + a1 * ws[128 + c + 0] + a2 * ws[256 + c + 0], 0.f);
    float oy = fmaxf(bs[c + 1] + a0 * ws[c + 1] + a1 * ws[128 + c + 1] + a2 * ws[256 + c + 1], 0.f);
    float oz = fmaxf(bs[c + 2] + a0 * ws[c + 2] + a1 * ws[128 + c + 2] + a2 * ws[256 + c + 2], 0.f);
    float ow = fmaxf(bs[c + 3] + a0 * ws[c + 3] + a1 * ws[128 + c + 3] + a2 * ws[256 + c + 3], 0.f);
    uint2 o;
    *(__half2*)&o.x = __floats2half2_rn(ox, oy);
    *(__half2*)&o.y = __floats2half2_rn(oz, ow);
    *(uint2*)&g_hbufA[row * 128 + c] = o;
}

// ---------------- fused layer 5: gemm5 + agg_out (grid barrier) ---------------
__global__ void __launch_bounds__(1024) k_l5(float* __restrict__ out,
                                             const float* __restrict__ W5,
                                             const float* __restrict__ b4,
                                             const float* __restrict__ b5) {
    __shared__ float ws[64];
    __shared__ float bs[64];
    const int t = threadIdx.x;
    if (t < 64) { ws[t] = W5[t]; bs[t] = b4[t]; }
    __syncthreads();
    const int i = blockIdx.x * 1024 + t;
    float s = 0.f;
    if (i < NN) {
#pragma unroll
        for (int k = 0; k < 64; k += 2) {
            float2 v = __half22float2(*(const __half2*)&g_hbufA[i * 64 + k]);
            s += fmaxf(v.x + bs[k], 0.f) * ws[k];
            s += fmaxf(v.y + bs[k + 1], 0.f) * ws[k + 1];
        }
        g_score[i] = s;
    }
    gbar(98);
    if (i < NN) {
        float d = g_dis[i];
        float acc = s * d * d + b5[0];
        int p1 = g_rowptr[i + 1];
        for (int p = g_rowptr[i]; p < p1; p++) {
            int2 eg = g_edge[p];
            acc += __int_as_float(eg.y) * g_score[eg.x];
        }
        out[i] = acc;
    }
}

// ---------------- fp16 mma.sync GEMM (layers 2-4), ldmatrix mainloop ----------
template <int K, int M, bool IN_T>
__global__ void __launch_bounds__(256) k_tcgemm(const __half* __restrict__ Wh,
                                                const float* __restrict__ inb) {
    constexpr int LDA = K + 8;
    constexpr int LDB = K + 8;
    constexpr int NT = M / 16;
    extern __shared__ __align__(16) __half sh[];
    __half* As = sh;                 // [128][LDA]
    __half* Bs = sh + 128 * LDA;     // [M][LDB]
    const int tid = threadIdx.x;
    const int rowBase = blockIdx.x * 128;

    // stage B: straight coalesced copy of pre-transposed fp16 image
    constexpr int BH = M * LDB;
    for (int idx = tid * 8; idx < BH; idx += 256 * 8)
        *(uint4*)&Bs[idx] = *(const uint4*)&Wh[idx];

    // stage A rows from fp16 input (bias+relu fold when IN_T)
    constexpr int K4 = K / 4;
#pragma unroll 4
    for (int idx = tid; idx < 128 * K4; idx += 256) {
        int r = idx / K4;
        int kc = (idx % K4) * 4;
        int gr = rowBase + r;
        uint2 u = make_uint2(0u, 0u);
        if (gr < NN) u = *(const uint2*)&g_hbufA[gr * K + kc];
        if (IN_T) {
            float2 p0 = __half22float2(*(__half2*)&u.x);
            float2 p1 = __half22float2(*(__half2*)&u.y);
            p0.x = fmaxf(p0.x + inb[kc + 0], 0.f);
            p0.y = fmaxf(p0.y + inb[kc + 1], 0.f);
            p1.x = fmaxf(p1.x + inb[kc + 2], 0.f);
            p1.y = fmaxf(p1.y + inb[kc + 3], 0.f);
            *(__half2*)&u.x = __floats2half2_rn(p0.x, p0.y);
            *(__half2*)&u.y = __floats2half2_rn(p1.x, p1.y);
        }
        *(uint2*)&As[r * LDA + kc] = u;
    }
    __syncthreads();

    const int wid = tid >> 5;
    const int lane = tid & 31;
    const int g = lane >> 2;
    const int tg = lane & 3;
    const int mRow = (wid & 3) * 32;
    const int nCol = (wid >> 2) * (M / 2);

    const int lrow = lane & 15;
    const int lko = (lane >> 4) << 3;
    const uint32_t aBase = (uint32_t)__cvta_generic_to_shared(As);
    const uint32_t bBase = (uint32_t)__cvta_generic_to_shared(Bs);
    uint32_t aAddr0 = aBase + (uint32_t)(((mRow + lrow) * LDA + lko) * 2);
    uint32_t aAddr1 = aAddr0 + 16 * LDA * 2;
    uint32_t bAddr[NT / 2];
#pragma unroll
    for (int p = 0; p < NT / 2; p++)
        bAddr[p] = bBase + (uint32_t)(((nCol + p * 16 + lrow) * LDB + lko) * 2);

    float acc[2][NT][4];
#pragma unroll
    for (int mt = 0; mt < 2; mt++)
#pragma unroll
        for (int nt = 0; nt < NT; nt++)
#pragma unroll
            for (int i = 0; i < 4; i++) acc[mt][nt][i] = 0.f;

#pragma unroll
    for (int k0 = 0; k0 < K; k0 += 16) {
        uint32_t a[2][4];
        LDSM4(a[0][0], a[0][1], a[0][2], a[0][3], aAddr0 + k0 * 2);
        LDSM4(a[1][0], a[1][1], a[1][2], a[1][3], aAddr1 + k0 * 2);
        uint32_t b[NT][2];
#pragma unroll
        for (int p = 0; p < NT / 2; p++) {
            uint32_t r0, r1, r2, r3;
            LDSM4(r0, r1, r2, r3, bAddr[p] + k0 * 2);
            b[2 * p][0] = r0; b[2 * p + 1][0] = r1;
            b[2 * p][1] = r2; b[2 * p + 1][1] = r3;
        }
#pragma unroll
        for (int mt = 0; mt < 2; mt++)
#pragma unroll
            for (int nt = 0; nt < NT; nt++) mma16816(acc[mt][nt], a[mt], b[nt]);
    }

#pragma unroll
    for (int mt = 0; mt < 2; mt++) {
        int r0 = rowBase + mRow + mt * 16 + g;
        int r1 = r0 + 8;
#pragma unroll
        for (int nt = 0; nt < NT; nt++) {
            int c = nCol + nt * 8 + 2 * tg;
            if (r0 < NN)
                *(__half2*)&g_hbuf[r0 * M + c] = __floats2half2_rn(acc[mt][nt][0], acc[mt][nt][1]);
            if (r1 < NN)
                *(__half2*)&g_hbuf[r1 * M + c] = __floats2half2_rn(acc[mt][nt][2], acc[mt][nt][3]);
        }
    }
}

// ---------------- launcher ----------------------------------------------------
extern "C" void kernel_launch(void* const* d_in, const int* in_sizes, int n_in,
                              void* d_out, int out_size) {
    const float* x  = (const float*)d_in[0];
    const int*   ei = (const int*)d_in[1];
    const float* W1 = (const float*)d_in[2];
    const float* b1 = (const float*)d_in[3];
    const float* W2 = (const float*)d_in[4];
    const float* b2 = (const float*)d_in[5];
    const float* W3 = (const float*)d_in[6];
    const float* b3 = (const float*)d_in[7];
    const float* W4 = (const float*)d_in[8];
    const float* b4 = (const float*)d_in[9];
    const float* W5 = (const float*)d_in[10];
    const float* b5 = (const float*)d_in[11];
    float* out = (float*)d_out;

    constexpr int SM2 = (128 * 136 + 128 * 136) * 2;  // 69632
    constexpr int SM3 = (128 * 136 + 64 * 136) * 2;   // 52224
    constexpr int SM4 = (128 * 72 + 64 * 72) * 2;     // 27648
    cudaFuncSetAttribute(k_tcgemm<128, 128, false>,
                         cudaFuncAttributeMaxDynamicSharedMemorySize, SM2);
    cudaFuncSetAttribute(k_tcgemm<128, 64, true>,
                         cudaFuncAttributeMaxDynamicSharedMemorySize, SM3);
    cudaFuncSetAttribute(k_tcgemm<64, 64, true>,
                         cudaFuncAttributeMaxDynamicSharedMemorySize, SM4);

    __half* hw2; cudaGetSymbolAddress((void**)&hw2, g_hW2);
    __half* hw3; cudaGetSymbolAddress((void**)&hw3, g_hW3);
    __half* hw4; cudaGetSymbolAddress((void**)&hw4, g_hW4);

    const int NB_N = (NN + 255) / 256;
    const int NB_E = (EE + 255) / 256;
    const int NB_W = (NN + 7) / 8;
    const int GB   = (NN + 127) / 128;

    // graph preprocessing (weight prep + x packing piggyback on hist)
    k_hist<<<NB_E, 256>>>(ei, x, W2, W3, W4);
    k_scan<<<98, 1024>>>();
    k_fill<<<NB_E, 256>>>(ei);

    // L1: A1 = Agg(x); H1 = relu(A1 @ W1 + b1) -> fp16
    k_agg0<<<NB_N, 256>>>();
    k_gemm1<<<(NN * 32 + 255) / 256, 256>>>(W1, b1);

    // L2: T2 = H1 @ W2 (fp16) ; A2 = Agg(T2) (fp16)
    k_tcgemm<128, 128, false><<<GB, 256, SM2>>>(hw2, nullptr);
    k_agg128<<<NB_W, 256>>>();

    // L3: T3 = relu(A2 + b2) @ W3 ; A3 = Agg(T3)
    k_tcgemm<128, 64, true><<<GB, 256, SM3>>>(hw3, b2);
    k_agg64<<<NB_W, 256>>>();

    // L4: T4 = relu(A3 + b3) @ W4 ; A4 = Agg(T4)
    k_tcgemm<64, 64, true><<<GB, 256, SM4>>>(hw4, b3);
    k_agg64<<<NB_W, 256>>>();

    // L5 fused: s = relu(A4 + b4) @ W5 ; out = Agg(s) + b5
    k_l5<<<98, 1024>>>(out, W5, b4, b5);
}

// round 14
// speedup vs baseline: 1.0604x; 1.0604x over previous
#include <cuda_runtime.h>
#include <cuda_fp16.h>
#include <cstdint>

#define NN 100000
#define EE 600000

// ---------------- scratch (static device globals; no runtime alloc) ----------
__device__ __half g_hbufA[NN * 128];  // fp16 GEMM inputs (agg outputs, H1)
__device__ __half g_hbuf[NN * 128];   // fp16 GEMM outputs (gather source)
__device__ float  g_score[NN];        // layer-5 per-node score
__device__ float  g_ax[NN * 3];
__device__ float4 g_x4[NN];           // padded copy of x for 16B gathers
__device__ int    g_cnt[NN];          // zero at load; re-zeroed by k_fill each run
__device__ int    g_rowptr[NN + 1];
__device__ float  g_dis[NN];
__device__ int2   g_edge[EE];         // CSR record: {src, __float_as_int(weight)}
__device__ int    g_rank[EE];
__device__ int    g_bsum[98];
__device__ unsigned g_barcnt = 0;
__device__ volatile unsigned g_barrel = 0;
// pre-transposed fp16 weight images: [n][k], row stride K+8 halves
__device__ __align__(16) __half g_hW2[128 * 136];
__device__ __align__(16) __half g_hW3[64 * 136];
__device__ __align__(16) __half g_hW4[64 * 72];

// ---------------- helpers ------------------------------------------------------
__device__ __forceinline__ void mma16816(float* c, const uint32_t* a, const uint32_t* b) {
    asm volatile(
        "mma.sync.aligned.m16n8k16.row.col.f32.f16.f16.f32 "
        "{%0,%1,%2,%3}, {%4,%5,%6,%7}, {%8,%9}, {%0,%1,%2,%3};"
        : "+f"(c[0]), "+f"(c[1]), "+f"(c[2]), "+f"(c[3])
        : "r"(a[0]), "r"(a[1]), "r"(a[2]), "r"(a[3]), "r"(b[0]), "r"(b[1]));
}
#define LDSM4(R0, R1, R2, R3, ADDR) \
    asm volatile("ldmatrix.sync.aligned.m8n8.x4.shared.b16 {%0,%1,%2,%3}, [%4];" \
                 : "=r"(R0), "=r"(R1), "=r"(R2), "=r"(R3) : "r"(ADDR))
__device__ __forceinline__ void h8_fma(float* acc, uint4 u, float w) {
    float2 p0 = __half22float2(*(__half2*)&u.x);
    float2 p1 = __half22float2(*(__half2*)&u.y);
    float2 p2 = __half22float2(*(__half2*)&u.z);
    float2 p3 = __half22float2(*(__half2*)&u.w);
    acc[0] += w * p0.x; acc[1] += w * p0.y;
    acc[2] += w * p1.x; acc[3] += w * p1.y;
    acc[4] += w * p2.x; acc[5] += w * p2.y;
    acc[6] += w * p3.x; acc[7] += w * p3.y;
}

// ---------------- hist (+ weight prep & x packing piggyback) ------------------
__global__ void k_hist(const int* __restrict__ ei, const float* __restrict__ x,
                       const float* __restrict__ W2, const float* __restrict__ W3,
                       const float* __restrict__ W4) {
    int e = blockIdx.x * blockDim.x + threadIdx.x;
    if (e < 128 * 128) {                   // W2: K=128, M=128
        int n = e >> 7, k = e & 127;
        g_hW2[n * 136 + k] = __float2half_rn(W2[k * 128 + n]);
    }
    if (e < 64 * 128) {                    // W3: K=128, M=64
        int n = e >> 7, k = e & 127;
        g_hW3[n * 136 + k] = __float2half_rn(W3[k * 64 + n]);
    }
    if (e < 64 * 64) {                     // W4: K=64, M=64
        int n = e >> 6, k = e & 63;
        g_hW4[n * 72 + k] = __float2half_rn(W4[k * 64 + n]);
    }
    if (e < NN)                            // pack x rows to 16B
        g_x4[e] = make_float4(x[e * 3 + 0], x[e * 3 + 1], x[e * 3 + 2], 0.f);
    if (e >= EE) return;
    int c = ei[EE + e];
    g_rank[e] = atomicAdd(&g_cnt[c], 1);
}
__global__ void __launch_bounds__(1024) k_scan() {
    const int t = threadIdx.x;
    const int lane = t & 31;
    const int w = t >> 5;
    const int i = blockIdx.x * 1024 + t;
    int v = (i < NN) ? g_cnt[i] : 0;

    int sc = v;
#pragma unroll
    for (int o = 1; o < 32; o <<= 1) {
        int u = __shfl_up_sync(0xFFFFFFFFu, sc, o);
        if (lane >= o) sc += u;
    }
    __shared__ int wsum[32];
    if (lane == 31) wsum[w] = sc;
    __syncthreads();
    if (w == 0) {
        int ws = wsum[lane];
#pragma unroll
        for (int o = 1; o < 32; o <<= 1) {
            int u = __shfl_up_sync(0xFFFFFFFFu, ws, o);
            if (lane >= o) ws += u;
        }
        wsum[lane] = ws;
    }
    __syncthreads();
    int incl = sc + ((w > 0) ? wsum[w - 1] : 0);
    if (t == 0) g_bsum[blockIdx.x] = wsum[31];

    __threadfence();
    __syncthreads();
    if (t == 0) {
        unsigned epoch = g_barrel;
        if (atomicAdd(&g_barcnt, 1u) == 97u) {
            g_barcnt = 0;
            __threadfence();
            g_barrel = epoch + 1;
        } else {
            while (g_barrel == epoch) {}
        }
    }
    __syncthreads();

    __shared__ int red[128];
    if (t < 128) red[t] = (t < blockIdx.x) ? g_bsum[t] : 0;
    __syncthreads();
#pragma unroll
    for (int o = 64; o > 0; o >>= 1) {
        if (t < o) red[t] += red[t + o];
        __syncthreads();
    }
    int excl = incl - v + red[0];
    if (i < NN) {
        g_rowptr[i] = excl;
        g_dis[i] = rsqrtf((float)(v + 1));
    }
    if (i == NN - 1) g_rowptr[NN] = excl + v;
}
__global__ void k_fill(const int* __restrict__ ei) {
    int e = blockIdx.x * blockDim.x + threadIdx.x;
    if (e < NN) g_cnt[e] = 0;
    if (e >= EE) return;
    int r = ei[e];
    int c = ei[EE + e];
    int p = g_rowptr[c] + g_rank[e];
    g_edge[p] = make_int2(r, __float_as_int(g_dis[r] * g_dis[c]));
}

// ---------------- aggregation kernels (gather, atomic-free) ------------------
__global__ void k_agg0() {
    int i = blockIdx.x * blockDim.x + threadIdx.x;
    if (i >= NN) return;
    float d = g_dis[i];
    float inv = d * d;
    float4 sx = g_x4[i];
    float a0 = sx.x * inv;
    float a1 = sx.y * inv;
    float a2 = sx.z * inv;
    int p1 = g_rowptr[i + 1];
    for (int p = g_rowptr[i]; p < p1; p++) {
        int2 eg = g_edge[p];
        float w = __int_as_float(eg.y);
        float4 v = g_x4[eg.x];
        a0 += w * v.x;
        a1 += w * v.y;
        a2 += w * v.z;
    }
    g_ax[i * 3 + 0] = a0;
    g_ax[i * 3 + 1] = a1;
    g_ax[i * 3 + 2] = a2;
}
// F=128 fp16: 16 lanes per node (uint4 = 8 cols each), 2 nodes per warp.
__global__ void k_agg128() {
    int t = threadIdx.x;
    int node = blockIdx.x * 16 + (t >> 4);
    if (node >= NN) return;
    int sl = t & 15;                 // sub-lane within node group
    int off = sl * 8;                // 8 halves = 16B
    float d = g_dis[node];
    float inv = d * d;
    float acc[8];
    uint4 su = *(const uint4*)&g_hbuf[node * 128 + off];
    {
        float2 p0 = __half22float2(*(__half2*)&su.x);
        float2 p1 = __half22float2(*(__half2*)&su.y);
        float2 p2 = __half22float2(*(__half2*)&su.z);
        float2 p3 = __half22float2(*(__half2*)&su.w);
        acc[0] = p0.x * inv; acc[1] = p0.y * inv;
        acc[2] = p1.x * inv; acc[3] = p1.y * inv;
        acc[4] = p2.x * inv; acc[5] = p2.y * inv;
        acc[6] = p3.x * inv; acc[7] = p3.y * inv;
    }
    int p1 = g_rowptr[node + 1];
    for (int p = g_rowptr[node]; p < p1; p++) {
        int2 eg = g_edge[p];
        float w = __int_as_float(eg.y);
        h8_fma(acc, *(const uint4*)&g_hbuf[eg.x * 128 + off], w);
    }
    uint4 o;
    *(__half2*)&o.x = __floats2half2_rn(acc[0], acc[1]);
    *(__half2*)&o.y = __floats2half2_rn(acc[2], acc[3]);
    *(__half2*)&o.z = __floats2half2_rn(acc[4], acc[5]);
    *(__half2*)&o.w = __floats2half2_rn(acc[6], acc[7]);
    *(uint4*)&g_hbufA[node * 128 + off] = o;
}
// F=64 fp16: 8 lanes per node (uint4 = 8 cols each), 4 nodes per warp.
__global__ void k_agg64() {
    int t = threadIdx.x;
    int node = blockIdx.x * 32 + (t >> 3);
    if (node >= NN) return;
    int sl = t & 7;
    int off = sl * 8;
    float d = g_dis[node];
    float inv = d * d;
    float acc[8];
    uint4 su = *(const uint4*)&g_hbuf[node * 64 + off];
    {
        float2 p0 = __half22float2(*(__half2*)&su.x);
        float2 p1 = __half22float2(*(__half2*)&su.y);
        float2 p2 = __half22float2(*(__half2*)&su.z);
        float2 p3 = __half22float2(*(__half2*)&su.w);
        acc[0] = p0.x * inv; acc[1] = p0.y * inv;
        acc[2] = p1.x * inv; acc[3] = p1.y * inv;
        acc[4] = p2.x * inv; acc[5] = p2.y * inv;
        acc[6] = p3.x * inv; acc[7] = p3.y * inv;
    }
    int p1 = g_rowptr[node + 1];
    for (int p = g_rowptr[node]; p < p1; p++) {
        int2 eg = g_edge[p];
        float w = __int_as_float(eg.y);
        h8_fma(acc, *(const uint4*)&g_hbuf[eg.x * 64 + off], w);
    }
    uint4 o;
    *(__half2*)&o.x = __floats2half2_rn(acc[0], acc[1]);
    *(__half2*)&o.y = __floats2half2_rn(acc[2], acc[3]);
    *(__half2*)&o.z = __floats2half2_rn(acc[4], acc[5]);
    *(__half2*)&o.w = __floats2half2_rn(acc[6], acc[7]);
    *(uint4*)&g_hbufA[node * 64 + off] = o;
}
__global__ void k_agg_out(float* __restrict__ out, const float* __restrict__ b5) {
    int i = blockIdx.x * blockDim.x + threadIdx.x;
    if (i >= NN) return;
    float d = g_dis[i];
    float acc = g_score[i] * d * d + b5[0];
    int p1 = g_rowptr[i + 1];
    for (int p = g_rowptr[i]; p < p1; p++) {
        int2 eg = g_edge[p];
        acc += __int_as_float(eg.y) * g_score[eg.x];
    }
    out[i] = acc;
}

// ---------------- small GEMMs (layers 1 and 5, SIMT) --------------------------
__global__ void k_gemm1(const float* __restrict__ W1, const float* __restrict__ b1) {
    __shared__ float ws[3 * 128];
    __shared__ float bs[128];
    for (int i = threadIdx.x; i < 384; i += 256) ws[i] = W1[i];
    if (threadIdx.x < 128) bs[threadIdx.x] = b1[threadIdx.x];
    __syncthreads();
    int gid = blockIdx.x * 256 + threadIdx.x;
    int row = gid >> 5;
    int c = (gid & 31) * 4;
    if (row >= NN) return;
    float a0 = g_ax[row * 3 + 0];
    float a1 = g_ax[row * 3 + 1];
    float a2 = g_ax[row * 3 + 2];
    float ox = fmaxf(bs[c + 0] + a0 * ws[c + 0] + a1 * ws[128 + c + 0] + a2 * ws[256 + c + 0], 0.f);
    float oy = fmaxf(bs[c + 1] + a0 * ws[c + 1] + a1 * ws[128 + c + 1] + a2 * ws[256 + c + 1], 0.f);
    float oz = fmaxf(bs[c + 2] + a0 * ws[c + 2] + a1 * ws[128 + c + 2] + a2 * ws[256 + c + 2], 0.f);
    float ow = fmaxf(bs[c + 3] + a0 * ws[c + 3] + a1 * ws[128 + c + 3] + a2 * ws[256 + c + 3], 0.f);
    uint2 o;
    *(__half2*)&o.x = __floats2half2_rn(ox, oy);
    *(__half2*)&o.y = __floats2half2_rn(oz, ow);
    *(uint2*)&g_hbufA[row * 128 + c] = o;
}
__global__ void k_gemm5(const float* __restrict__ W5, const float* __restrict__ b4) {
    __shared__ float ws[64];
    __shared__ float bs[64];
    if (threadIdx.x < 64) {
        ws[threadIdx.x] = W5[threadIdx.x];
        bs[threadIdx.x] = b4[threadIdx.x];
    }
    __syncthreads();
    int row = blockIdx.x * blockDim.x + threadIdx.x;
    if (row >= NN) return;
    float acc = 0.f;
#pragma unroll
    for (int k = 0; k < 64; k += 2) {
        float2 v = __half22float2(*(const __half2*)&g_hbufA[row * 64 + k]);
        acc += fmaxf(v.x + bs[k], 0.f) * ws[k];
        acc += fmaxf(v.y + bs[k + 1], 0.f) * ws[k + 1];
    }
    g_score[row] = acc;
}

// ---------------- fp16 mma.sync GEMM (layers 2-4), ldmatrix mainloop ----------
template <int K, int M, bool IN_T>
__global__ void __launch_bounds__(256) k_tcgemm(const __half* __restrict__ Wh,
                                                const float* __restrict__ inb) {
    constexpr int LDA = K + 8;
    constexpr int LDB = K + 8;
    constexpr int NT = M / 16;
    extern __shared__ __align__(16) __half sh[];
    __half* As = sh;                 // [128][LDA]
    __half* Bs = sh + 128 * LDA;     // [M][LDB]
    const int tid = threadIdx.x;
    const int rowBase = blockIdx.x * 128;

    // stage B: straight coalesced copy of pre-transposed fp16 image
    constexpr int BH = M * LDB;
    for (int idx = tid * 8; idx < BH; idx += 256 * 8)
        *(uint4*)&Bs[idx] = *(const uint4*)&Wh[idx];

    // stage A rows from fp16 input (bias+relu fold when IN_T)
    constexpr int K4 = K / 4;
#pragma unroll 4
    for (int idx = tid; idx < 128 * K4; idx += 256) {
        int r = idx / K4;
        int kc = (idx % K4) * 4;
        int gr = rowBase + r;
        uint2 u = make_uint2(0u, 0u);
        if (gr < NN) u = *(const uint2*)&g_hbufA[gr * K + kc];
        if (IN_T) {
            float2 p0 = __half22float2(*(__half2*)&u.x);
            float2 p1 = __half22float2(*(__half2*)&u.y);
            p0.x = fmaxf(p0.x + inb[kc + 0], 0.f);
            p0.y = fmaxf(p0.y + inb[kc + 1], 0.f);
            p1.x = fmaxf(p1.x + inb[kc + 2], 0.f);
            p1.y = fmaxf(p1.y + inb[kc + 3], 0.f);
            *(__half2*)&u.x = __floats2half2_rn(p0.x, p0.y);
            *(__half2*)&u.y = __floats2half2_rn(p1.x, p1.y);
        }
        *(uint2*)&As[r * LDA + kc] = u;
    }
    __syncthreads();

    const int wid = tid >> 5;
    const int lane = tid & 31;
    const int g = lane >> 2;
    const int tg = lane & 3;
    const int mRow = (wid & 3) * 32;
    const int nCol = (wid >> 2) * (M / 2);

    const int lrow = lane & 15;
    const int lko = (lane >> 4) << 3;
    const uint32_t aBase = (uint32_t)__cvta_generic_to_shared(As);
    const uint32_t bBase = (uint32_t)__cvta_generic_to_shared(Bs);
    uint32_t aAddr0 = aBase + (uint32_t)(((mRow + lrow) * LDA + lko) * 2);
    uint32_t aAddr1 = aAddr0 + 16 * LDA * 2;
    uint32_t bAddr[NT / 2];
#pragma unroll
    for (int p = 0; p < NT / 2; p++)
        bAddr[p] = bBase + (uint32_t)(((nCol + p * 16 + lrow) * LDB + lko) * 2);

    float acc[2][NT][4];
#pragma unroll
    for (int mt = 0; mt < 2; mt++)
#pragma unroll
        for (int nt = 0; nt < NT; nt++)
#pragma unroll
            for (int i = 0; i < 4; i++) acc[mt][nt][i] = 0.f;

#pragma unroll
    for (int k0 = 0; k0 < K; k0 += 16) {
        uint32_t a[2][4];
        LDSM4(a[0][0], a[0][1], a[0][2], a[0][3], aAddr0 + k0 * 2);
        LDSM4(a[1][0], a[1][1], a[1][2], a[1][3], aAddr1 + k0 * 2);
        uint32_t b[NT][2];
#pragma unroll
        for (int p = 0; p < NT / 2; p++) {
            uint32_t r0, r1, r2, r3;
            LDSM4(r0, r1, r2, r3, bAddr[p] + k0 * 2);
            b[2 * p][0] = r0; b[2 * p + 1][0] = r1;
            b[2 * p][1] = r2; b[2 * p + 1][1] = r3;
        }
#pragma unroll
        for (int mt = 0; mt < 2; mt++)
#pragma unroll
            for (int nt = 0; nt < NT; nt++) mma16816(acc[mt][nt], a[mt], b[nt]);
    }

#pragma unroll
    for (int mt = 0; mt < 2; mt++) {
        int r0 = rowBase + mRow + mt * 16 + g;
        int r1 = r0 + 8;
#pragma unroll
        for (int nt = 0; nt < NT; nt++) {
            int c = nCol + nt * 8 + 2 * tg;
            if (r0 < NN)
                *(__half2*)&g_hbuf[r0 * M + c] = __floats2half2_rn(acc[mt][nt][0], acc[mt][nt][1]);
            if (r1 < NN)
                *(__half2*)&g_hbuf[r1 * M + c] = __floats2half2_rn(acc[mt][nt][2], acc[mt][nt][3]);
        }
    }
}

// ---------------- launcher ----------------------------------------------------
extern "C" void kernel_launch(void* const* d_in, const int* in_sizes, int n_in,
                              void* d_out, int out_size) {
    const float* x  = (const float*)d_in[0];
    const int*   ei = (const int*)d_in[1];
    const float* W1 = (const float*)d_in[2];
    const float* b1 = (const float*)d_in[3];
    const float* W2 = (const float*)d_in[4];
    const float* b2 = (const float*)d_in[5];
    const float* W3 = (const float*)d_in[6];
    const float* b3 = (const float*)d_in[7];
    const float* W4 = (const float*)d_in[8];
    const float* b4 = (const float*)d_in[9];
    const float* W5 = (const float*)d_in[10];
    const float* b5 = (const float*)d_in[11];
    float* out = (float*)d_out;

    constexpr int SM2 = (128 * 136 + 128 * 136) * 2;  // 69632
    constexpr int SM3 = (128 * 136 + 64 * 136) * 2;   // 52224
    constexpr int SM4 = (128 * 72 + 64 * 72) * 2;     // 27648
    cudaFuncSetAttribute(k_tcgemm<128, 128, false>,
                         cudaFuncAttributeMaxDynamicSharedMemorySize, SM2);
    cudaFuncSetAttribute(k_tcgemm<128, 64, true>,
                         cudaFuncAttributeMaxDynamicSharedMemorySize, SM3);
    cudaFuncSetAttribute(k_tcgemm<64, 64, true>,
                         cudaFuncAttributeMaxDynamicSharedMemorySize, SM4);

    __half* hw2; cudaGetSymbolAddress((void**)&hw2, g_hW2);
    __half* hw3; cudaGetSymbolAddress((void**)&hw3, g_hW3);
    __half* hw4; cudaGetSymbolAddress((void**)&hw4, g_hW4);

    const int NB_N = (NN + 255) / 256;
    const int NB_E = (EE + 255) / 256;
    const int GB   = (NN + 127) / 128;

    // graph preprocessing (weight prep + x packing piggyback on hist)
    k_hist<<<NB_E, 256>>>(ei, x, W2, W3, W4);
    k_scan<<<98, 1024>>>();
    k_fill<<<NB_E, 256>>>(ei);

    // L1: A1 = Agg(x); H1 = relu(A1 @ W1 + b1) -> fp16
    k_agg0<<<NB_N, 256>>>();
    k_gemm1<<<(NN * 32 + 255) / 256, 256>>>(W1, b1);

    // L2: T2 = H1 @ W2 (fp16) ; A2 = Agg(T2) (fp16)
    k_tcgemm<128, 128, false><<<GB, 256, SM2>>>(hw2, nullptr);
    k_agg128<<<(NN + 15) / 16, 256>>>();

    // L3: T3 = relu(A2 + b2) @ W3 ; A3 = Agg(T3)
    k_tcgemm<128, 64, true><<<GB, 256, SM3>>>(hw3, b2);
    k_agg64<<<(NN + 31) / 32, 256>>>();

    // L4: T4 = relu(A3 + b3) @ W4 ; A4 = Agg(T4)
    k_tcgemm<64, 64, true><<<GB, 256, SM4>>>(hw4, b3);
    k_agg64<<<(NN + 31) / 32, 256>>>();

    // L5: s = relu(A4 + b4) @ W5 ; out = Agg(s) + b5
    k_gemm5<<<NB_N, 256>>>(W5, b4);
    k_agg_out<<<NB_N, 256>>>(out, b5);
}

// round 15
// speedup vs baseline: 1.2062x; 1.1374x over previous
#include <cuda_runtime.h>
#include <cuda_fp16.h>
#include <cstdint>

#define NN 100000
#define EE 600000

// ---------------- scratch (static device globals; no runtime alloc) ----------
__device__ __half g_hbufA[NN * 128];  // fp16 GEMM inputs (agg outputs, H1)
__device__ __half g_hbuf[NN * 128];   // fp16 GEMM outputs (gather source)
__device__ float  g_score[NN];        // layer-5 per-node score
__device__ float4 g_x4[NN];           // padded copy of x for 16B gathers
__device__ int    g_cnt[NN];          // zero at load; re-zeroed by k_fill each run
__device__ int    g_rowptr[NN + 1];
__device__ float  g_dis[NN];
__device__ int2   g_edge[EE];         // CSR record: {src, __float_as_int(weight)}
__device__ int    g_rank[EE];
__device__ int    g_bsum[98];
__device__ unsigned g_barcnt = 0;
__device__ volatile unsigned g_barrel = 0;
// pre-transposed fp16 weight images: [n][k], row stride K+8 halves
__device__ __align__(16) __half g_hW2[128 * 136];
__device__ __align__(16) __half g_hW3[64 * 136];
__device__ __align__(16) __half g_hW4[64 * 72];

// ---------------- helpers ------------------------------------------------------
__device__ __forceinline__ void mma16816(float* c, const uint32_t* a, const uint32_t* b) {
    asm volatile(
        "mma.sync.aligned.m16n8k16.row.col.f32.f16.f16.f32 "
        "{%0,%1,%2,%3}, {%4,%5,%6,%7}, {%8,%9}, {%0,%1,%2,%3};"
        : "+f"(c[0]), "+f"(c[1]), "+f"(c[2]), "+f"(c[3])
        : "r"(a[0]), "r"(a[1]), "r"(a[2]), "r"(a[3]), "r"(b[0]), "r"(b[1]));
}
#define LDSM4(R0, R1, R2, R3, ADDR) \
    asm volatile("ldmatrix.sync.aligned.m8n8.x4.shared.b16 {%0,%1,%2,%3}, [%4];" \
                 : "=r"(R0), "=r"(R1), "=r"(R2), "=r"(R3) : "r"(ADDR))
__device__ __forceinline__ void h8_fma(float* acc, uint4 u, float w) {
    float2 p0 = __half22float2(*(__half2*)&u.x);
    float2 p1 = __half22float2(*(__half2*)&u.y);
    float2 p2 = __half22float2(*(__half2*)&u.z);
    float2 p3 = __half22float2(*(__half2*)&u.w);
    acc[0] += w * p0.x; acc[1] += w * p0.y;
    acc[2] += w * p1.x; acc[3] += w * p1.y;
    acc[4] += w * p2.x; acc[5] += w * p2.y;
    acc[6] += w * p3.x; acc[7] += w * p3.y;
}

// ---------------- hist (+ weight prep & x packing piggyback) ------------------
__global__ void k_hist(const int* __restrict__ ei, const float* __restrict__ x,
                       const float* __restrict__ W2, const float* __restrict__ W3,
                       const float* __restrict__ W4) {
    int e = blockIdx.x * blockDim.x + threadIdx.x;
    if (e < 128 * 128) {                   // W2: K=128, M=128
        int n = e >> 7, k = e & 127;
        g_hW2[n * 136 + k] = __float2half_rn(W2[k * 128 + n]);
    }
    if (e < 64 * 128) {                    // W3: K=128, M=64
        int n = e >> 7, k = e & 127;
        g_hW3[n * 136 + k] = __float2half_rn(W3[k * 64 + n]);
    }
    if (e < 64 * 64) {                     // W4: K=64, M=64
        int n = e >> 6, k = e & 63;
        g_hW4[n * 72 + k] = __float2half_rn(W4[k * 64 + n]);
    }
    if (e < NN)                            // pack x rows to 16B
        g_x4[e] = make_float4(x[e * 3 + 0], x[e * 3 + 1], x[e * 3 + 2], 0.f);
    if (e >= EE) return;
    int c = ei[EE + e];
    g_rank[e] = atomicAdd(&g_cnt[c], 1);
}
__global__ void __launch_bounds__(1024) k_scan() {
    const int t = threadIdx.x;
    const int lane = t & 31;
    const int w = t >> 5;
    const int i = blockIdx.x * 1024 + t;
    int v = (i < NN) ? g_cnt[i] : 0;

    int sc = v;
#pragma unroll
    for (int o = 1; o < 32; o <<= 1) {
        int u = __shfl_up_sync(0xFFFFFFFFu, sc, o);
        if (lane >= o) sc += u;
    }
    __shared__ int wsum[32];
    if (lane == 31) wsum[w] = sc;
    __syncthreads();
    if (w == 0) {
        int ws = wsum[lane];
#pragma unroll
        for (int o = 1; o < 32; o <<= 1) {
            int u = __shfl_up_sync(0xFFFFFFFFu, ws, o);
            if (lane >= o) ws += u;
        }
        wsum[lane] = ws;
    }
    __syncthreads();
    int incl = sc + ((w > 0) ? wsum[w - 1] : 0);
    if (t == 0) g_bsum[blockIdx.x] = wsum[31];

    __threadfence();
    __syncthreads();
    if (t == 0) {
        unsigned epoch = g_barrel;
        if (atomicAdd(&g_barcnt, 1u) == 97u) {
            g_barcnt = 0;
            __threadfence();
            g_barrel = epoch + 1;
        } else {
            while (g_barrel == epoch) {}
        }
    }
    __syncthreads();

    __shared__ int red[128];
    if (t < 128) red[t] = (t < blockIdx.x) ? g_bsum[t] : 0;
    __syncthreads();
#pragma unroll
    for (int o = 64; o > 0; o >>= 1) {
        if (t < o) red[t] += red[t + o];
        __syncthreads();
    }
    int excl = incl - v + red[0];
    if (i < NN) {
        g_rowptr[i] = excl;
        g_dis[i] = rsqrtf((float)(v + 1));
    }
    if (i == NN - 1) g_rowptr[NN] = excl + v;
}
__global__ void k_fill(const int* __restrict__ ei) {
    int e = blockIdx.x * blockDim.x + threadIdx.x;
    if (e < NN) g_cnt[e] = 0;
    if (e >= EE) return;
    int r = ei[e];
    int c = ei[EE + e];
    int p = g_rowptr[c] + g_rank[e];
    g_edge[p] = make_int2(r, __float_as_int(g_dis[r] * g_dis[c]));
}

// ---------------- fused layer 1: agg(x) + GEMM 3->128 + bias + relu -----------
// Block owns 256 nodes. Phase 1: thread-per-node aggregation -> SMEM.
// Phase 2: k_gemm1's warp-per-node output pattern reading SMEM (block-local).
__global__ void __launch_bounds__(256) k_l1(const float* __restrict__ W1,
                                            const float* __restrict__ b1) {
    __shared__ float ws[384];
    __shared__ float bs[128];
    __shared__ float sa0[256], sa1[256], sa2[256];
    const int t = threadIdx.x;
    for (int i = t; i < 384; i += 256) ws[i] = W1[i];
    if (t < 128) bs[t] = b1[t];

    const int node0 = blockIdx.x * 256;
    const int i = node0 + t;
    float a0 = 0.f, a1 = 0.f, a2 = 0.f;
    if (i < NN) {
        float d = g_dis[i];
        float inv = d * d;
        float4 sx = g_x4[i];
        a0 = sx.x * inv;
        a1 = sx.y * inv;
        a2 = sx.z * inv;
        int p1 = g_rowptr[i + 1];
        for (int p = g_rowptr[i]; p < p1; p++) {
            int2 eg = g_edge[p];
            float w = __int_as_float(eg.y);
            float4 v = g_x4[eg.x];
            a0 += w * v.x;
            a1 += w * v.y;
            a2 += w * v.z;
        }
    }
    sa0[t] = a0; sa1[t] = a1; sa2[t] = a2;
    __syncthreads();

    const int c = (t & 31) * 4;
    const int wrp = t >> 5;
#pragma unroll 8
    for (int pass = 0; pass < 32; pass++) {
        int ln = pass * 8 + wrp;
        int node = node0 + ln;
        if (node < NN) {
            float v0 = sa0[ln], v1 = sa1[ln], v2 = sa2[ln];
            float ox = fmaxf(bs[c + 0] + v0 * ws[c + 0] + v1 * ws[128 + c + 0] + v2 * ws[256 + c + 0], 0.f);
            float oy = fmaxf(bs[c + 1] + v0 * ws[c + 1] + v1 * ws[128 + c + 1] + v2 * ws[256 + c + 1], 0.f);
            float oz = fmaxf(bs[c + 2] + v0 * ws[c + 2] + v1 * ws[128 + c + 2] + v2 * ws[256 + c + 2], 0.f);
            float ow = fmaxf(bs[c + 3] + v0 * ws[c + 3] + v1 * ws[128 + c + 3] + v2 * ws[256 + c + 3], 0.f);
            uint2 o;
            *(__half2*)&o.x = __floats2half2_rn(ox, oy);
            *(__half2*)&o.y = __floats2half2_rn(oz, ow);
            *(uint2*)&g_hbufA[node * 128 + c] = o;
        }
    }
}

// ---------------- aggregation kernels (gather, atomic-free) ------------------
// F=128 fp16: 16 lanes per node (uint4 = 8 cols each), 2 nodes per warp.
__global__ void k_agg128() {
    int t = threadIdx.x;
    int node = blockIdx.x * 16 + (t >> 4);
    if (node >= NN) return;
    int sl = t & 15;
    int off = sl * 8;
    float d = g_dis[node];
    float inv = d * d;
    float acc[8];
    uint4 su = *(const uint4*)&g_hbuf[node * 128 + off];
    {
        float2 p0 = __half22float2(*(__half2*)&su.x);
        float2 p1 = __half22float2(*(__half2*)&su.y);
        float2 p2 = __half22float2(*(__half2*)&su.z);
        float2 p3 = __half22float2(*(__half2*)&su.w);
        acc[0] = p0.x * inv; acc[1] = p0.y * inv;
        acc[2] = p1.x * inv; acc[3] = p1.y * inv;
        acc[4] = p2.x * inv; acc[5] = p2.y * inv;
        acc[6] = p3.x * inv; acc[7] = p3.y * inv;
    }
    int p1 = g_rowptr[node + 1];
    for (int p = g_rowptr[node]; p < p1; p++) {
        int2 eg = g_edge[p];
        float w = __int_as_float(eg.y);
        h8_fma(acc, *(const uint4*)&g_hbuf[eg.x * 128 + off], w);
    }
    uint4 o;
    *(__half2*)&o.x = __floats2half2_rn(acc[0], acc[1]);
    *(__half2*)&o.y = __floats2half2_rn(acc[2], acc[3]);
    *(__half2*)&o.z = __floats2half2_rn(acc[4], acc[5]);
    *(__half2*)&o.w = __floats2half2_rn(acc[6], acc[7]);
    *(uint4*)&g_hbufA[node * 128 + off] = o;
}
// F=64 fp16: 8 lanes per node (uint4 = 8 cols each), 4 nodes per warp.
__global__ void k_agg64() {
    int t = threadIdx.x;
    int node = blockIdx.x * 32 + (t >> 3);
    if (node >= NN) return;
    int sl = t & 7;
    int off = sl * 8;
    float d = g_dis[node];
    float inv = d * d;
    float acc[8];
    uint4 su = *(const uint4*)&g_hbuf[node * 64 + off];
    {
        float2 p0 = __half22float2(*(__half2*)&su.x);
        float2 p1 = __half22float2(*(__half2*)&su.y);
        float2 p2 = __half22float2(*(__half2*)&su.z);
        float2 p3 = __half22float2(*(__half2*)&su.w);
        acc[0] = p0.x * inv; acc[1] = p0.y * inv;
        acc[2] = p1.x * inv; acc[3] = p1.y * inv;
        acc[4] = p2.x * inv; acc[5] = p2.y * inv;
        acc[6] = p3.x * inv; acc[7] = p3.y * inv;
    }
    int p1 = g_rowptr[node + 1];
    for (int p = g_rowptr[node]; p < p1; p++) {
        int2 eg = g_edge[p];
        float w = __int_as_float(eg.y);
        h8_fma(acc, *(const uint4*)&g_hbuf[eg.x * 64 + off], w);
    }
    uint4 o;
    *(__half2*)&o.x = __floats2half2_rn(acc[0], acc[1]);
    *(__half2*)&o.y = __floats2half2_rn(acc[2], acc[3]);
    *(__half2*)&o.z = __floats2half2_rn(acc[4], acc[5]);
    *(__half2*)&o.w = __floats2half2_rn(acc[6], acc[7]);
    *(uint4*)&g_hbufA[node * 64 + off] = o;
}
// L4 agg variant: fuse layer-5 dot product. Writes g_score only (fp32 path).
__global__ void k_agg64s(const float* __restrict__ W5, const float* __restrict__ b4) {
    __shared__ float ws[64];
    __shared__ float bs[64];
    int t = threadIdx.x;
    if (t < 64) { ws[t] = W5[t]; bs[t] = b4[t]; }
    __syncthreads();
    int node = blockIdx.x * 32 + (t >> 3);
    if (node >= NN) return;
    int sl = t & 7;
    int off = sl * 8;
    float d = g_dis[node];
    float inv = d * d;
    float acc[8];
    uint4 su = *(const uint4*)&g_hbuf[node * 64 + off];
    {
        float2 p0 = __half22float2(*(__half2*)&su.x);
        float2 p1 = __half22float2(*(__half2*)&su.y);
        float2 p2 = __half22float2(*(__half2*)&su.z);
        float2 p3 = __half22float2(*(__half2*)&su.w);
        acc[0] = p0.x * inv; acc[1] = p0.y * inv;
        acc[2] = p1.x * inv; acc[3] = p1.y * inv;
        acc[4] = p2.x * inv; acc[5] = p2.y * inv;
        acc[6] = p3.x * inv; acc[7] = p3.y * inv;
    }
    int p1 = g_rowptr[node + 1];
    for (int p = g_rowptr[node]; p < p1; p++) {
        int2 eg = g_edge[p];
        float w = __int_as_float(eg.y);
        h8_fma(acc, *(const uint4*)&g_hbuf[eg.x * 64 + off], w);
    }
    // layer-5 partial dot: relu(acc + b4) . W5 over this lane's 8 cols
    float s = 0.f;
#pragma unroll
    for (int j = 0; j < 8; j++)
        s += fmaxf(acc[j] + bs[off + j], 0.f) * ws[off + j];
    // reduce across the 8 sub-lanes of this node
#pragma unroll
    for (int o = 4; o > 0; o >>= 1)
        s += __shfl_down_sync(0xFFFFFFFFu, s, o, 8);
    if (sl == 0) g_score[node] = s;
}
__global__ void k_agg_out(float* __restrict__ out, const float* __restrict__ b5) {
    int i = blockIdx.x * blockDim.x + threadIdx.x;
    if (i >= NN) return;
    float d = g_dis[i];
    float acc = g_score[i] * d * d + b5[0];
    int p1 = g_rowptr[i + 1];
    for (int p = g_rowptr[i]; p < p1; p++) {
        int2 eg = g_edge[p];
        acc += __int_as_float(eg.y) * g_score[eg.x];
    }
    out[i] = acc;
}

// ---------------- fp16 mma.sync GEMM (layers 2-4), ldmatrix mainloop ----------
template <int K, int M, bool IN_T>
__global__ void __launch_bounds__(256) k_tcgemm(const __half* __restrict__ Wh,
                                                const float* __restrict__ inb) {
    constexpr int LDA = K + 8;
    constexpr int LDB = K + 8;
    constexpr int NT = M / 16;
    extern __shared__ __align__(16) __half sh[];
    __half* As = sh;                 // [128][LDA]
    __half* Bs = sh + 128 * LDA;     // [M][LDB]
    const int tid = threadIdx.x;
    const int rowBase = blockIdx.x * 128;

    constexpr int BH = M * LDB;
    for (int idx = tid * 8; idx < BH; idx += 256 * 8)
        *(uint4*)&Bs[idx] = *(const uint4*)&Wh[idx];

    constexpr int K4 = K / 4;
#pragma unroll 4
    for (int idx = tid; idx < 128 * K4; idx += 256) {
        int r = idx / K4;
        int kc = (idx % K4) * 4;
        int gr = rowBase + r;
        uint2 u = make_uint2(0u, 0u);
        if (gr < NN) u = *(const uint2*)&g_hbufA[gr * K + kc];
        if (IN_T) {
            float2 p0 = __half22float2(*(__half2*)&u.x);
            float2 p1 = __half22float2(*(__half2*)&u.y);
            p0.x = fmaxf(p0.x + inb[kc + 0], 0.f);
            p0.y = fmaxf(p0.y + inb[kc + 1], 0.f);
            p1.x = fmaxf(p1.x + inb[kc + 2], 0.f);
            p1.y = fmaxf(p1.y + inb[kc + 3], 0.f);
            *(__half2*)&u.x = __floats2half2_rn(p0.x, p0.y);
            *(__half2*)&u.y = __floats2half2_rn(p1.x, p1.y);
        }
        *(uint2*)&As[r * LDA + kc] = u;
    }
    __syncthreads();

    const int wid = tid >> 5;
    const int lane = tid & 31;
    const int g = lane >> 2;
    const int tg = lane & 3;
    const int mRow = (wid & 3) * 32;
    const int nCol = (wid >> 2) * (M / 2);

    const int lrow = lane & 15;
    const int lko = (lane >> 4) << 3;
    const uint32_t aBase = (uint32_t)__cvta_generic_to_shared(As);
    const uint32_t bBase = (uint32_t)__cvta_generic_to_shared(Bs);
    uint32_t aAddr0 = aBase + (uint32_t)(((mRow + lrow) * LDA + lko) * 2);
    uint32_t aAddr1 = aAddr0 + 16 * LDA * 2;
    uint32_t bAddr[NT / 2];
#pragma unroll
    for (int p = 0; p < NT / 2; p++)
        bAddr[p] = bBase + (uint32_t)(((nCol + p * 16 + lrow) * LDB + lko) * 2);

    float acc[2][NT][4];
#pragma unroll
    for (int mt = 0; mt < 2; mt++)
#pragma unroll
        for (int nt = 0; nt < NT; nt++)
#pragma unroll
            for (int i = 0; i < 4; i++) acc[mt][nt][i] = 0.f;

#pragma unroll
    for (int k0 = 0; k0 < K; k0 += 16) {
        uint32_t a[2][4];
        LDSM4(a[0][0], a[0][1], a[0][2], a[0][3], aAddr0 + k0 * 2);
        LDSM4(a[1][0], a[1][1], a[1][2], a[1][3], aAddr1 + k0 * 2);
        uint32_t b[NT][2];
#pragma unroll
        for (int p = 0; p < NT / 2; p++) {
            uint32_t r0, r1, r2, r3;
            LDSM4(r0, r1, r2, r3, bAddr[p] + k0 * 2);
            b[2 * p][0] = r0; b[2 * p + 1][0] = r1;
            b[2 * p][1] = r2; b[2 * p + 1][1] = r3;
        }
#pragma unroll
        for (int mt = 0; mt < 2; mt++)
#pragma unroll
            for (int nt = 0; nt < NT; nt++) mma16816(acc[mt][nt], a[mt], b[nt]);
    }

#pragma unroll
    for (int mt = 0; mt < 2; mt++) {
        int r0 = rowBase + mRow + mt * 16 + g;
        int r1 = r0 + 8;
#pragma unroll
        for (int nt = 0; nt < NT; nt++) {
            int c = nCol + nt * 8 + 2 * tg;
            if (r0 < NN)
                *(__half2*)&g_hbuf[r0 * M + c] = __floats2half2_rn(acc[mt][nt][0], acc[mt][nt][1]);
            if (r1 < NN)
                *(__half2*)&g_hbuf[r1 * M + c] = __floats2half2_rn(acc[mt][nt][2], acc[mt][nt][3]);
        }
    }
}

// ---------------- launcher ----------------------------------------------------
extern "C" void kernel_launch(void* const* d_in, const int* in_sizes, int n_in,
                              void* d_out, int out_size) {
    const float* x  = (const float*)d_in[0];
    const int*   ei = (const int*)d_in[1];
    const float* W1 = (const float*)d_in[2];
    const float* b1 = (const float*)d_in[3];
    const float* W2 = (const float*)d_in[4];
    const float* b2 = (const float*)d_in[5];
    const float* W3 = (const float*)d_in[6];
    const float* b3 = (const float*)d_in[7];
    const float* W4 = (const float*)d_in[8];
    const float* b4 = (const float*)d_in[9];
    const float* W5 = (const float*)d_in[10];
    const float* b5 = (const float*)d_in[11];
    float* out = (float*)d_out;

    constexpr int SM2 = (128 * 136 + 128 * 136) * 2;  // 69632
    constexpr int SM3 = (128 * 136 + 64 * 136) * 2;   // 52224
    constexpr int SM4 = (128 * 72 + 64 * 72) * 2;     // 27648
    cudaFuncSetAttribute(k_tcgemm<128, 128, false>,
                         cudaFuncAttributeMaxDynamicSharedMemorySize, SM2);
    cudaFuncSetAttribute(k_tcgemm<128, 64, true>,
                         cudaFuncAttributeMaxDynamicSharedMemorySize, SM3);
    cudaFuncSetAttribute(k_tcgemm<64, 64, true>,
                         cudaFuncAttributeMaxDynamicSharedMemorySize, SM4);

    __half* hw2; cudaGetSymbolAddress((void**)&hw2, g_hW2);
    __half* hw3; cudaGetSymbolAddress((void**)&hw3, g_hW3);
    __half* hw4; cudaGetSymbolAddress((void**)&hw4, g_hW4);

    const int NB_N = (NN + 255) / 256;
    const int NB_E = (EE + 255) / 256;
    const int GB   = (NN + 127) / 128;

    // graph preprocessing (weight prep + x packing piggyback on hist)
    k_hist<<<NB_E, 256>>>(ei, x, W2, W3, W4);
    k_scan<<<98, 1024>>>();
    k_fill<<<NB_E, 256>>>(ei);

    // L1 fused: A1 = Agg(x); H1 = relu(A1 @ W1 + b1) -> fp16
    k_l1<<<NB_N, 256>>>(W1, b1);

    // L2: T2 = H1 @ W2 (fp16) ; A2 = Agg(T2) (fp16)
    k_tcgemm<128, 128, false><<<GB, 256, SM2>>>(hw2, nullptr);
    k_agg128<<<(NN + 15) / 16, 256>>>();

    // L3: T3 = relu(A2 + b2) @ W3 ; A3 = Agg(T3)
    k_tcgemm<128, 64, true><<<GB, 256, SM3>>>(hw3, b2);
    k_agg64<<<(NN + 31) / 32, 256>>>();

    // L4: T4 = relu(A3 + b3) @ W4 ; A4+L5 fused: s = relu(A4 + b4) @ W5
    k_tcgemm<64, 64, true><<<GB, 256, SM4>>>(hw4, b3);
    k_agg64s<<<(NN + 31) / 32, 256>>>(W5, b4);

    // out = Agg(s) + b5
    k_agg_out<<<NB_N, 256>>>(out, b5);
}

// round 16
// speedup vs baseline: 1.2484x; 1.0350x over previous
#include <cuda_runtime.h>
#include <cuda_fp16.h>
#include <cstdint>

#define NN 100000
#define EE 600000

// ---------------- scratch (static device globals; no runtime alloc) ----------
__device__ __half g_hbufA[NN * 128];  // fp16 GEMM inputs (agg outputs, H1)
__device__ __half g_hbuf[NN * 128];   // fp16 GEMM outputs (gather source)
__device__ float  g_score[NN];        // layer-5 per-node score
__device__ float4 g_x4[NN];           // padded copy of x for 16B gathers
__device__ int    g_cnt[NN];          // zero at load; re-zeroed by k_fill each run
__device__ int    g_rowptr[NN + 1];
__device__ float  g_dis[NN];
__device__ int2   g_edge[EE];         // CSR record: {src, __float_as_int(weight)}
__device__ int    g_rank[EE];
__device__ int    g_bsum[98];
__device__ unsigned g_barcnt = 0;
__device__ volatile unsigned g_barrel = 0;
// pre-transposed fp16 weight images: [n][k], row stride K+8 halves
__device__ __align__(16) __half g_hW2[128 * 136];
__device__ __align__(16) __half g_hW3[64 * 136];
__device__ __align__(16) __half g_hW4[64 * 72];

// ---------------- helpers ------------------------------------------------------
__device__ __forceinline__ void mma16816(float* c, const uint32_t* a, const uint32_t* b) {
    asm volatile(
        "mma.sync.aligned.m16n8k16.row.col.f32.f16.f16.f32 "
        "{%0,%1,%2,%3}, {%4,%5,%6,%7}, {%8,%9}, {%0,%1,%2,%3};"
        : "+f"(c[0]), "+f"(c[1]), "+f"(c[2]), "+f"(c[3])
        : "r"(a[0]), "r"(a[1]), "r"(a[2]), "r"(a[3]), "r"(b[0]), "r"(b[1]));
}
#define LDSM4(R0, R1, R2, R3, ADDR) \
    asm volatile("ldmatrix.sync.aligned.m8n8.x4.shared.b16 {%0,%1,%2,%3}, [%4];" \
                 : "=r"(R0), "=r"(R1), "=r"(R2), "=r"(R3) : "r"(ADDR))
__device__ __forceinline__ void h8_fma(float* acc, uint4 u, float w) {
    float2 p0 = __half22float2(*(__half2*)&u.x);
    float2 p1 = __half22float2(*(__half2*)&u.y);
    float2 p2 = __half22float2(*(__half2*)&u.z);
    float2 p3 = __half22float2(*(__half2*)&u.w);
    acc[0] += w * p0.x; acc[1] += w * p0.y;
    acc[2] += w * p1.x; acc[3] += w * p1.y;
    acc[4] += w * p2.x; acc[5] += w * p2.y;
    acc[6] += w * p3.x; acc[7] += w * p3.y;
}

// ---------------- hist (+ weight prep & x packing piggyback) ------------------
__global__ void k_hist(const int* __restrict__ ei, const float* __restrict__ x,
                       const float* __restrict__ W2, const float* __restrict__ W3,
                       const float* __restrict__ W4) {
    int e = blockIdx.x * blockDim.x + threadIdx.x;
    if (e < 128 * 128) {                   // W2: K=128, M=128
        int n = e >> 7, k = e & 127;
        g_hW2[n * 136 + k] = __float2half_rn(W2[k * 128 + n]);
    }
    if (e < 64 * 128) {                    // W3: K=128, M=64
        int n = e >> 7, k = e & 127;
        g_hW3[n * 136 + k] = __float2half_rn(W3[k * 64 + n]);
    }
    if (e < 64 * 64) {                     // W4: K=64, M=64
        int n = e >> 6, k = e & 63;
        g_hW4[n * 72 + k] = __float2half_rn(W4[k * 64 + n]);
    }
    if (e < NN)                            // pack x rows to 16B
        g_x4[e] = make_float4(x[e * 3 + 0], x[e * 3 + 1], x[e * 3 + 2], 0.f);
    if (e >= EE) return;
    int c = ei[EE + e];
    g_rank[e] = atomicAdd(&g_cnt[c], 1);
}
__global__ void __launch_bounds__(1024) k_scan() {
    const int t = threadIdx.x;
    const int lane = t & 31;
    const int w = t >> 5;
    const int i = blockIdx.x * 1024 + t;
    int v = (i < NN) ? g_cnt[i] : 0;

    int sc = v;
#pragma unroll
    for (int o = 1; o < 32; o <<= 1) {
        int u = __shfl_up_sync(0xFFFFFFFFu, sc, o);
        if (lane >= o) sc += u;
    }
    __shared__ int wsum[32];
    if (lane == 31) wsum[w] = sc;
    __syncthreads();
    if (w == 0) {
        int ws = wsum[lane];
#pragma unroll
        for (int o = 1; o < 32; o <<= 1) {
            int u = __shfl_up_sync(0xFFFFFFFFu, ws, o);
            if (lane >= o) ws += u;
        }
        wsum[lane] = ws;
    }
    __syncthreads();
    int incl = sc + ((w > 0) ? wsum[w - 1] : 0);
    if (t == 0) g_bsum[blockIdx.x] = wsum[31];

    __threadfence();
    __syncthreads();
    if (t == 0) {
        unsigned epoch = g_barrel;
        if (atomicAdd(&g_barcnt, 1u) == 97u) {
            g_barcnt = 0;
            __threadfence();
            g_barrel = epoch + 1;
        } else {
            while (g_barrel == epoch) {}
        }
    }
    __syncthreads();

    __shared__ int red[128];
    if (t < 128) red[t] = (t < blockIdx.x) ? g_bsum[t] : 0;
    __syncthreads();
#pragma unroll
    for (int o = 64; o > 0; o >>= 1) {
        if (t < o) red[t] += red[t + o];
        __syncthreads();
    }
    int excl = incl - v + red[0];
    if (i < NN) {
        g_rowptr[i] = excl;
        g_dis[i] = rsqrtf((float)(v + 1));
    }
    if (i == NN - 1) g_rowptr[NN] = excl + v;
}
__global__ void k_fill(const int* __restrict__ ei) {
    int e = blockIdx.x * blockDim.x + threadIdx.x;
    if (e < NN) g_cnt[e] = 0;
    if (e >= EE) return;
    int r = ei[e];
    int c = ei[EE + e];
    int p = g_rowptr[c] + g_rank[e];
    g_edge[p] = make_int2(r, __float_as_int(g_dis[r] * g_dis[c]));
}

// ---------------- fused layer 1: agg(x) + GEMM 3->128 + bias + relu -----------
// Block owns 256 nodes. Phase 1: thread-per-node aggregation -> SMEM.
// Phase 2: warp-per-node outputs; per-thread weights REGISTER-HOISTED.
__global__ void __launch_bounds__(256) k_l1(const float* __restrict__ W1,
                                            const float* __restrict__ b1) {
    __shared__ float sa0[256], sa1[256], sa2[256];
    const int t = threadIdx.x;
    const int c = (t & 31) * 4;
    // hoist this thread's 16 weight/bias values into registers (loop-invariant)
    float w0[4], w1[4], w2[4], bb[4];
#pragma unroll
    for (int j = 0; j < 4; j++) {
        w0[j] = W1[c + j];
        w1[j] = W1[128 + c + j];
        w2[j] = W1[256 + c + j];
        bb[j] = b1[c + j];
    }

    const int node0 = blockIdx.x * 256;
    const int i = node0 + t;
    float a0 = 0.f, a1 = 0.f, a2 = 0.f;
    if (i < NN) {
        float d = g_dis[i];
        float inv = d * d;
        float4 sx = g_x4[i];
        a0 = sx.x * inv;
        a1 = sx.y * inv;
        a2 = sx.z * inv;
        int p1 = g_rowptr[i + 1];
        for (int p = g_rowptr[i]; p < p1; p++) {
            int2 eg = g_edge[p];
            float w = __int_as_float(eg.y);
            float4 v = g_x4[eg.x];
            a0 += w * v.x;
            a1 += w * v.y;
            a2 += w * v.z;
        }
    }
    sa0[t] = a0; sa1[t] = a1; sa2[t] = a2;
    __syncthreads();

    const int wrp = t >> 5;
#pragma unroll 8
    for (int pass = 0; pass < 32; pass++) {
        int ln = pass * 8 + wrp;
        int node = node0 + ln;
        if (node < NN) {
            float v0 = sa0[ln], v1 = sa1[ln], v2 = sa2[ln];
            float ox = fmaxf(bb[0] + v0 * w0[0] + v1 * w1[0] + v2 * w2[0], 0.f);
            float oy = fmaxf(bb[1] + v0 * w0[1] + v1 * w1[1] + v2 * w2[1], 0.f);
            float oz = fmaxf(bb[2] + v0 * w0[2] + v1 * w1[2] + v2 * w2[2], 0.f);
            float ow = fmaxf(bb[3] + v0 * w0[3] + v1 * w1[3] + v2 * w2[3], 0.f);
            uint2 o;
            *(__half2*)&o.x = __floats2half2_rn(ox, oy);
            *(__half2*)&o.y = __floats2half2_rn(oz, ow);
            *(uint2*)&g_hbufA[node * 128 + c] = o;
        }
    }
}

// ---------------- aggregation kernels (gather, atomic-free) ------------------
// F=128 fp16: 16 lanes per node (uint4 = 8 cols each), 2 nodes per warp.
__global__ void k_agg128() {
    int t = threadIdx.x;
    int node = blockIdx.x * 16 + (t >> 4);
    if (node >= NN) return;
    int sl = t & 15;
    int off = sl * 8;
    float d = g_dis[node];
    float inv = d * d;
    float acc[8];
    uint4 su = *(const uint4*)&g_hbuf[node * 128 + off];
    {
        float2 p0 = __half22float2(*(__half2*)&su.x);
        float2 p1 = __half22float2(*(__half2*)&su.y);
        float2 p2 = __half22float2(*(__half2*)&su.z);
        float2 p3 = __half22float2(*(__half2*)&su.w);
        acc[0] = p0.x * inv; acc[1] = p0.y * inv;
        acc[2] = p1.x * inv; acc[3] = p1.y * inv;
        acc[4] = p2.x * inv; acc[5] = p2.y * inv;
        acc[6] = p3.x * inv; acc[7] = p3.y * inv;
    }
    int p1 = g_rowptr[node + 1];
    for (int p = g_rowptr[node]; p < p1; p++) {
        int2 eg = g_edge[p];
        float w = __int_as_float(eg.y);
        h8_fma(acc, *(const uint4*)&g_hbuf[eg.x * 128 + off], w);
    }
    uint4 o;
    *(__half2*)&o.x = __floats2half2_rn(acc[0], acc[1]);
    *(__half2*)&o.y = __floats2half2_rn(acc[2], acc[3]);
    *(__half2*)&o.z = __floats2half2_rn(acc[4], acc[5]);
    *(__half2*)&o.w = __floats2half2_rn(acc[6], acc[7]);
    *(uint4*)&g_hbufA[node * 128 + off] = o;
}
// F=64 fp16: 8 lanes per node (uint4 = 8 cols each), 4 nodes per warp.
__global__ void k_agg64() {
    int t = threadIdx.x;
    int node = blockIdx.x * 32 + (t >> 3);
    if (node >= NN) return;
    int sl = t & 7;
    int off = sl * 8;
    float d = g_dis[node];
    float inv = d * d;
    float acc[8];
    uint4 su = *(const uint4*)&g_hbuf[node * 64 + off];
    {
        float2 p0 = __half22float2(*(__half2*)&su.x);
        float2 p1 = __half22float2(*(__half2*)&su.y);
        float2 p2 = __half22float2(*(__half2*)&su.z);
        float2 p3 = __half22float2(*(__half2*)&su.w);
        acc[0] = p0.x * inv; acc[1] = p0.y * inv;
        acc[2] = p1.x * inv; acc[3] = p1.y * inv;
        acc[4] = p2.x * inv; acc[5] = p2.y * inv;
        acc[6] = p3.x * inv; acc[7] = p3.y * inv;
    }
    int p1 = g_rowptr[node + 1];
    for (int p = g_rowptr[node]; p < p1; p++) {
        int2 eg = g_edge[p];
        float w = __int_as_float(eg.y);
        h8_fma(acc, *(const uint4*)&g_hbuf[eg.x * 64 + off], w);
    }
    uint4 o;
    *(__half2*)&o.x = __floats2half2_rn(acc[0], acc[1]);
    *(__half2*)&o.y = __floats2half2_rn(acc[2], acc[3]);
    *(__half2*)&o.z = __floats2half2_rn(acc[4], acc[5]);
    *(__half2*)&o.w = __floats2half2_rn(acc[6], acc[7]);
    *(uint4*)&g_hbufA[node * 64 + off] = o;
}
// L4 agg variant: fuse layer-5 dot product. Writes g_score only (fp32 path).
__global__ void k_agg64s(const float* __restrict__ W5, const float* __restrict__ b4) {
    __shared__ float ws[64];
    __shared__ float bs[64];
    int t = threadIdx.x;
    if (t < 64) { ws[t] = W5[t]; bs[t] = b4[t]; }
    __syncthreads();
    int node = blockIdx.x * 32 + (t >> 3);
    if (node >= NN) return;
    int sl = t & 7;
    int off = sl * 8;
    float d = g_dis[node];
    float inv = d * d;
    float acc[8];
    uint4 su = *(const uint4*)&g_hbuf[node * 64 + off];
    {
        float2 p0 = __half22float2(*(__half2*)&su.x);
        float2 p1 = __half22float2(*(__half2*)&su.y);
        float2 p2 = __half22float2(*(__half2*)&su.z);
        float2 p3 = __half22float2(*(__half2*)&su.w);
        acc[0] = p0.x * inv; acc[1] = p0.y * inv;
        acc[2] = p1.x * inv; acc[3] = p1.y * inv;
        acc[4] = p2.x * inv; acc[5] = p2.y * inv;
        acc[6] = p3.x * inv; acc[7] = p3.y * inv;
    }
    int p1 = g_rowptr[node + 1];
    for (int p = g_rowptr[node]; p < p1; p++) {
        int2 eg = g_edge[p];
        float w = __int_as_float(eg.y);
        h8_fma(acc, *(const uint4*)&g_hbuf[eg.x * 64 + off], w);
    }
    float s = 0.f;
#pragma unroll
    for (int j = 0; j < 8; j++)
        s += fmaxf(acc[j] + bs[off + j], 0.f) * ws[off + j];
#pragma unroll
    for (int o = 4; o > 0; o >>= 1)
        s += __shfl_down_sync(0xFFFFFFFFu, s, o, 8);
    if (sl == 0) g_score[node] = s;
}
__global__ void k_agg_out(float* __restrict__ out, const float* __restrict__ b5) {
    int i = blockIdx.x * blockDim.x + threadIdx.x;
    if (i >= NN) return;
    float d = g_dis[i];
    float acc = g_score[i] * d * d + b5[0];
    int p1 = g_rowptr[i + 1];
    for (int p = g_rowptr[i]; p < p1; p++) {
        int2 eg = g_edge[p];
        acc += __int_as_float(eg.y) * g_score[eg.x];
    }
    out[i] = acc;
}

// ---------------- fp16 mma.sync GEMM (layers 2-4), ldmatrix mainloop ----------
template <int K, int M, bool IN_T>
__global__ void __launch_bounds__(256) k_tcgemm(const __half* __restrict__ Wh,
                                                const float* __restrict__ inb) {
    constexpr int LDA = K + 8;
    constexpr int LDB = K + 8;
    constexpr int NT = M / 16;
    extern __shared__ __align__(16) __half sh[];
    __half* As = sh;                 // [128][LDA]
    __half* Bs = sh + 128 * LDA;     // [M][LDB]
    const int tid = threadIdx.x;
    const int rowBase = blockIdx.x * 128;

    constexpr int BH = M * LDB;
    for (int idx = tid * 8; idx < BH; idx += 256 * 8)
        *(uint4*)&Bs[idx] = *(const uint4*)&Wh[idx];

    constexpr int K4 = K / 4;
#pragma unroll 4
    for (int idx = tid; idx < 128 * K4; idx += 256) {
        int r = idx / K4;
        int kc = (idx % K4) * 4;
        int gr = rowBase + r;
        uint2 u = make_uint2(0u, 0u);
        if (gr < NN) u = *(const uint2*)&g_hbufA[gr * K + kc];
        if (IN_T) {
            float2 p0 = __half22float2(*(__half2*)&u.x);
            float2 p1 = __half22float2(*(__half2*)&u.y);
            p0.x = fmaxf(p0.x + inb[kc + 0], 0.f);
            p0.y = fmaxf(p0.y + inb[kc + 1], 0.f);
            p1.x = fmaxf(p1.x + inb[kc + 2], 0.f);
            p1.y = fmaxf(p1.y + inb[kc + 3], 0.f);
            *(__half2*)&u.x = __floats2half2_rn(p0.x, p0.y);
            *(__half2*)&u.y = __floats2half2_rn(p1.x, p1.y);
        }
        *(uint2*)&As[r * LDA + kc] = u;
    }
    __syncthreads();

    const int wid = tid >> 5;
    const int lane = tid & 31;
    const int g = lane >> 2;
    const int tg = lane & 3;
    const int mRow = (wid & 3) * 32;
    const int nCol = (wid >> 2) * (M / 2);

    const int lrow = lane & 15;
    const int lko = (lane >> 4) << 3;
    const uint32_t aBase = (uint32_t)__cvta_generic_to_shared(As);
    const uint32_t bBase = (uint32_t)__cvta_generic_to_shared(Bs);
    uint32_t aAddr0 = aBase + (uint32_t)(((mRow + lrow) * LDA + lko) * 2);
    uint32_t aAddr1 = aAddr0 + 16 * LDA * 2;
    uint32_t bAddr[NT / 2];
#pragma unroll
    for (int p = 0; p < NT / 2; p++)
        bAddr[p] = bBase + (uint32_t)(((nCol + p * 16 + lrow) * LDB + lko) * 2);

    float acc[2][NT][4];
#pragma unroll
    for (int mt = 0; mt < 2; mt++)
#pragma unroll
        for (int nt = 0; nt < NT; nt++)
#pragma unroll
            for (int i = 0; i < 4; i++) acc[mt][nt][i] = 0.f;

#pragma unroll
    for (int k0 = 0; k0 < K; k0 += 16) {
        uint32_t a[2][4];
        LDSM4(a[0][0], a[0][1], a[0][2], a[0][3], aAddr0 + k0 * 2);
        LDSM4(a[1][0], a[1][1], a[1][2], a[1][3], aAddr1 + k0 * 2);
        uint32_t b[NT][2];
#pragma unroll
        for (int p = 0; p < NT / 2; p++) {
            uint32_t r0, r1, r2, r3;
            LDSM4(r0, r1, r2, r3, bAddr[p] + k0 * 2);
            b[2 * p][0] = r0; b[2 * p + 1][0] = r1;
            b[2 * p][1] = r2; b[2 * p + 1][1] = r3;
        }
#pragma unroll
        for (int mt = 0; mt < 2; mt++)
#pragma unroll
            for (int nt = 0; nt < NT; nt++) mma16816(acc[mt][nt], a[mt], b[nt]);
    }

#pragma unroll
    for (int mt = 0; mt < 2; mt++) {
        int r0 = rowBase + mRow + mt * 16 + g;
        int r1 = r0 + 8;
#pragma unroll
        for (int nt = 0; nt < NT; nt++) {
            int c = nCol + nt * 8 + 2 * tg;
            if (r0 < NN)
                *(__half2*)&g_hbuf[r0 * M + c] = __floats2half2_rn(acc[mt][nt][0], acc[mt][nt][1]);
            if (r1 < NN)
                *(__half2*)&g_hbuf[r1 * M + c] = __floats2half2_rn(acc[mt][nt][2], acc[mt][nt][3]);
        }
    }
}

// ---------------- launcher ----------------------------------------------------
extern "C" void kernel_launch(void* const* d_in, const int* in_sizes, int n_in,
                              void* d_out, int out_size) {
    const float* x  = (const float*)d_in[0];
    const int*   ei = (const int*)d_in[1];
    const float* W1 = (const float*)d_in[2];
    const float* b1 = (const float*)d_in[3];
    const float* W2 = (const float*)d_in[4];
    const float* b2 = (const float*)d_in[5];
    const float* W3 = (const float*)d_in[6];
    const float* b3 = (const float*)d_in[7];
    const float* W4 = (const float*)d_in[8];
    const float* b4 = (const float*)d_in[9];
    const float* W5 = (const float*)d_in[10];
    const float* b5 = (const float*)d_in[11];
    float* out = (float*)d_out;

    constexpr int SM2 = (128 * 136 + 128 * 136) * 2;  // 69632
    constexpr int SM3 = (128 * 136 + 64 * 136) * 2;   // 52224
    constexpr int SM4 = (128 * 72 + 64 * 72) * 2;     // 27648
    cudaFuncSetAttribute(k_tcgemm<128, 128, false>,
                         cudaFuncAttributeMaxDynamicSharedMemorySize, SM2);
    cudaFuncSetAttribute(k_tcgemm<128, 64, true>,
                         cudaFuncAttributeMaxDynamicSharedMemorySize, SM3);
    cudaFuncSetAttribute(k_tcgemm<64, 64, true>,
                         cudaFuncAttributeMaxDynamicSharedMemorySize, SM4);

    __half* hw2; cudaGetSymbolAddress((void**)&hw2, g_hW2);
    __half* hw3; cudaGetSymbolAddress((void**)&hw3, g_hW3);
    __half* hw4; cudaGetSymbolAddress((void**)&hw4, g_hW4);

    const int NB_N = (NN + 255) / 256;
    const int NB_E = (EE + 255) / 256;
    const int GB   = (NN + 127) / 128;

    // graph preprocessing (weight prep + x packing piggyback on hist)
    k_hist<<<NB_E, 256>>>(ei, x, W2, W3, W4);
    k_scan<<<98, 1024>>>();
    k_fill<<<NB_E, 256>>>(ei);

    // L1 fused: A1 = Agg(x); H1 = relu(A1 @ W1 + b1) -> fp16
    k_l1<<<NB_N, 256>>>(W1, b1);

    // L2: T2 = H1 @ W2 (fp16) ; A2 = Agg(T2) (fp16)
    k_tcgemm<128, 128, false><<<GB, 256, SM2>>>(hw2, nullptr);
    k_agg128<<<(NN + 15) / 16, 256>>>();

    // L3: T3 = relu(A2 + b2) @ W3 ; A3 = Agg(T3)
    k_tcgemm<128, 64, true><<<GB, 256, SM3>>>(hw3, b2);
    k_agg64<<<(NN + 31) / 32, 256>>>();

    // L4: T4 = relu(A3 + b3) @ W4 ; A4+L5 fused: s = relu(A4 + b4) @ W5
    k_tcgemm<64, 64, true><<<GB, 256, SM4>>>(hw4, b3);
    k_agg64s<<<(NN + 31) / 32, 256>>>(W5, b4);

    // out = Agg(s) + b5
    k_agg_out<<<NB_N, 256>>>(out, b5);
}